// round 15
// baseline (speedup 1.0000x reference)
#include <cuda_runtime.h>
#include <cuda_fp16.h>
#include <cmath>

// ---------------- packed f32x2 helpers (Blackwell sm_100+) ----------------
__device__ __forceinline__ unsigned long long pack2(float lo, float hi) {
    unsigned long long r;
    asm("mov.b64 %0, {%1, %2};" : "=l"(r) : "f"(lo), "f"(hi));
    return r;
}
__device__ __forceinline__ void unpack2(unsigned long long v, float& lo, float& hi) {
    asm("mov.b64 {%0, %1}, %2;" : "=f"(lo), "=f"(hi) : "l"(v));
}
__device__ __forceinline__ unsigned long long fma2(unsigned long long a,
                                                   unsigned long long b,
                                                   unsigned long long c) {
    unsigned long long d;
    asm("fma.rn.f32x2 %0, %1, %2, %3;" : "=l"(d) : "l"(a), "l"(b), "l"(c));
    return d;
}
__device__ __forceinline__ unsigned long long mul2(unsigned long long a,
                                                   unsigned long long b) {
    unsigned long long d;
    asm("mul.rn.f32x2 %0, %1, %2;" : "=l"(d) : "l"(a), "l"(b));
    return d;
}

// ---------------- half2 / MUFU helpers ----------------
__device__ __forceinline__ unsigned int h2u(__half2 h) {
    unsigned int u; memcpy(&u, &h, 4); return u;
}
__device__ __forceinline__ unsigned int tanh_h2u(unsigned int x) {
    unsigned int r;
    asm("tanh.approx.f16x2 %0, %1;" : "=r"(r) : "r"(x));
    return r;
}
__device__ __forceinline__ float tanh_f32(float x) {
    float y;
    asm("tanh.approx.f32 %0, %1;" : "=f"(y) : "f"(x));
    return y;
}
// b_out is pre-scaled by 0.5, so sigmoid(2d) = 0.5 + 0.5*tanh(d): 2 instrs
__device__ __forceinline__ float sigmoid_prescaled(float half_x) {
    return fmaf(0.5f, tanh_f32(half_x), 0.5f);
}
// pack two f32 into f16x2: result = {lo: 'lo', hi: 'hi'}
__device__ __forceinline__ unsigned int f2h2(float hi, float lo) {
    unsigned int r;
    asm("cvt.rn.f16x2.f32 %0, %1, %2;" : "=r"(r) : "f"(hi), "f"(lo));
    return r;
}

// ---------------- mma: D[16,8] = A[16,8]*B[8,8] ----------------
__device__ __forceinline__ void mma8_f16(unsigned int& d0, unsigned int& d1,
                                         unsigned int a0, unsigned int a1,
                                         unsigned int b) {
    unsigned int r0, r1;
    asm("mma.sync.aligned.m16n8k8.row.col.f16.f16.f16.f16 "
        "{%0,%1}, {%2,%3}, {%4}, {%5,%6};"
        : "=r"(r0), "=r"(r1)
        : "r"(a0), "r"(a1), "r"(b), "r"(0u), "r"(0u));
    d0 = r0; d1 = r1;
}
__device__ __forceinline__ void mma8_f32(float& d0, float& d1, float& d2, float& d3,
                                         unsigned int a0, unsigned int a1,
                                         unsigned int b) {
    asm("mma.sync.aligned.m16n8k8.row.col.f32.f16.f16.f32 "
        "{%0,%1,%2,%3}, {%4,%5}, {%6}, {%7,%8,%9,%10};"
        : "=f"(d0), "=f"(d1), "=f"(d2), "=f"(d3)
        : "r"(a0), "r"(a1), "r"(b),
          "f"(0.0f), "f"(0.0f), "f"(0.0f), "f"(0.0f));
}

// Folded tanh poly (host-fitted, deg 13): tanh(x) ~= x * sum_{i=0}^{6} k[i] x^{2i},
// accurate on |x| <= xmax; inputs clamped (scalar FMNMX) first.
struct PolyC { float k[7]; float xmax; };

#define TILP 8

__global__ void __launch_bounds__(256)
mlp_mma_poly_kernel(const float2* __restrict__ x2,
                    const float* __restrict__ W_in,
                    const float* __restrict__ W_h,
                    const float* __restrict__ W_out,
                    float* __restrict__ out,
                    int ntiles, PolyC pc)
{
    const int lane = threadIdx.x & 31;
    const int g = lane >> 2;   // 0..7
    const int c = lane & 3;    // 0..3
    const int warp = (blockIdx.x * blockDim.x + threadIdx.x) >> 5;
    const int nwarps = (gridDim.x * blockDim.x) >> 5;

    // B fragments: b = {W[g][2c], W[g][2c+1]}
    unsigned int b_in = (c == 0)
        ? h2u(__floats2half2_rn(__ldg(W_in + 2 * g), __ldg(W_in + 2 * g + 1)))
        : 0u;
    unsigned int b_h =
        h2u(__floats2half2_rn(__ldg(W_h + 8 * g + 2 * c), __ldg(W_h + 8 * g + 2 * c + 1)));
    // Output weights pre-scaled by 0.5 (folds the sigmoid's x/2)
    unsigned int b_out = (g < 3)
        ? h2u(__floats2half2_rn(0.5f * __ldg(W_out + 8 * g + 2 * c),
                                0.5f * __ldg(W_out + 8 * g + 2 * c + 1)))
        : 0u;

    // duplicated-packed folded coefficients (f32x2)
    unsigned long long K[7];
#pragma unroll
    for (int i = 0; i < 7; i++) K[i] = pack2(pc.k[i], pc.k[i]);
    const float xmax = pc.xmax;

    for (int t0 = warp * TILP; t0 < ntiles; t0 += nwarps * TILP) {
        unsigned int h0[TILP], h1[TILP];

        // ---- input layer: f16 mma + MUFU tanh ----
#pragma unroll
        for (int u = 0; u < TILP; u++) {
            int base = (t0 + u) * 16;
            float2 p0 = __ldg(x2 + base + g);
            float2 p1 = __ldg(x2 + base + 8 + g);
            unsigned int a0 = (c == 0) ? h2u(__floats2half2_rn(p0.x, p0.y)) : 0u;
            unsigned int a1 = (c == 0) ? h2u(__floats2half2_rn(p1.x, p1.y)) : 0u;
            unsigned int d0, d1;
            mma8_f16(d0, d1, a0, a1, b_in);
            h0[u] = tanh_h2u(d0);
            h1[u] = tanh_h2u(d1);
        }

        // ---- 4 hidden layers: alternate poly (fma pipe) / MUFU ----
#pragma unroll
        for (int l = 0; l < 4; l++) {
            if ((l & 1) == 0) {
                // POLY layer
#pragma unroll
                for (int u = 0; u < TILP; u++) {
                    float d0, d1, d2, d3;
                    mma8_f32(d0, d1, d2, d3, h0[u], h1[u], b_h);
                    d0 = fminf(fmaxf(d0, -xmax), xmax);
                    d1 = fminf(fmaxf(d1, -xmax), xmax);
                    d2 = fminf(fmaxf(d2, -xmax), xmax);
                    d3 = fminf(fmaxf(d3, -xmax), xmax);
                    unsigned long long vA = pack2(d0, d1);
                    unsigned long long vB = pack2(d2, d3);
                    unsigned long long uA = mul2(vA, vA);
                    unsigned long long uB = mul2(vB, vB);
                    unsigned long long pA = fma2(K[6], uA, K[5]);
                    unsigned long long pB = fma2(K[6], uB, K[5]);
                    pA = fma2(pA, uA, K[4]);  pB = fma2(pB, uB, K[4]);
                    pA = fma2(pA, uA, K[3]);  pB = fma2(pB, uB, K[3]);
                    pA = fma2(pA, uA, K[2]);  pB = fma2(pB, uB, K[2]);
                    pA = fma2(pA, uA, K[1]);  pB = fma2(pB, uB, K[1]);
                    pA = fma2(pA, uA, K[0]);  pB = fma2(pB, uB, K[0]);
                    unsigned long long rA = mul2(pA, vA);
                    unsigned long long rB = mul2(pB, vB);
                    float r0, r1, r2, r3;
                    unpack2(rA, r0, r1);
                    unpack2(rB, r2, r3);
                    h0[u] = f2h2(r1, r0);   // {lo=col 2c, hi=col 2c+1}
                    h1[u] = f2h2(r3, r2);
                }
            } else {
                // MUFU layer
#pragma unroll
                for (int u = 0; u < TILP; u++) {
                    unsigned int d0, d1;
                    mma8_f16(d0, d1, h0[u], h1[u], b_h);
                    h0[u] = tanh_h2u(d0);
                    h1[u] = tanh_h2u(d1);
                }
            }
        }

        // ---- output layer (weights pre-halved) + sigmoid + scalar stores ----
#pragma unroll
        for (int u = 0; u < TILP; u++) {
            float d0, d1, d2, d3;
            mma8_f32(d0, d1, d2, d3, h0[u], h1[u], b_out);
            int base = (t0 + u) * 16;
            if (c < 2) {
                float s0 = sigmoid_prescaled(d0);
                float s1 = sigmoid_prescaled(d1);
                float s2 = sigmoid_prescaled(d2);
                float s3 = sigmoid_prescaled(d3);
                long long r0 = base + g;
                long long r1 = base + 8 + g;
                if (c == 0) {
                    out[r0 * 3 + 0] = s0;
                    out[r0 * 3 + 1] = s1;
                    out[r1 * 3 + 0] = s2;
                    out[r1 * 3 + 1] = s3;
                } else {
                    out[r0 * 3 + 2] = s0;
                    out[r1 * 3 + 2] = s2;
                }
            }
        }
    }
}

// ---------------- host: weighted LS fit of tanh(x)/x on [0, xmax] ----------------
static void fit_tanh_poly_folded(double xmax, float* kf, int NCc) {
    const int NS = 6000;
    double ATA[8][8] = {{0}}, ATy[8] = {0};
    for (int j = 1; j <= NS; j++) {
        double x = xmax * j / NS;
        double u = (x / xmax) * (x / xmax);
        double y = tanh(x) / x;
        double w2 = x * x;
        double pu[8];
        pu[0] = 1.0;
        for (int i = 1; i < NCc; i++) pu[i] = pu[i - 1] * u;
        for (int a = 0; a < NCc; a++) {
            for (int b = 0; b < NCc; b++) ATA[a][b] += w2 * pu[a] * pu[b];
            ATy[a] += w2 * pu[a] * y;
        }
    }
    for (int k = 0; k < NCc; k++) {
        int piv = k;
        for (int r = k + 1; r < NCc; r++)
            if (fabs(ATA[r][k]) > fabs(ATA[piv][k])) piv = r;
        if (piv != k) {
            for (int cc = 0; cc < NCc; cc++) {
                double t = ATA[k][cc]; ATA[k][cc] = ATA[piv][cc]; ATA[piv][cc] = t;
            }
            double t = ATy[k]; ATy[k] = ATy[piv]; ATy[piv] = t;
        }
        for (int r = k + 1; r < NCc; r++) {
            double f = ATA[r][k] / ATA[k][k];
            for (int cc = k; cc < NCc; cc++) ATA[r][cc] -= f * ATA[k][cc];
            ATy[r] -= f * ATy[k];
        }
    }
    double sol[8];
    for (int k = NCc - 1; k >= 0; k--) {
        double s = ATy[k];
        for (int cc = k + 1; cc < NCc; cc++) s -= ATA[k][cc] * sol[cc];
        sol[k] = s / ATA[k][k];
    }
    double scale = 1.0;
    for (int i = 0; i < NCc; i++) {
        kf[i] = (float)(sol[i] * scale);
        scale /= (xmax * xmax);
    }
}

extern "C" void kernel_launch(void* const* d_in, const int* in_sizes, int n_in,
                              void* d_out, int out_size)
{
    const float* x     = (const float*)d_in[0];  // [N, 2]
    const float* W_in  = (const float*)d_in[1];  // [8, 2]
    const float* W_h   = (const float*)d_in[2];  // [8, 8]
    const float* W_out = (const float*)d_in[3];  // [3, 8]

    int n_pixels = in_sizes[0] / 2;      // 16777216
    int ntiles = n_pixels / 16;          // 1048576, divisible by TILP=8

    const double XMAX = 3.35;
    PolyC pc;
    fit_tanh_poly_folded(XMAX, pc.k, 7);
    pc.xmax = (float)XMAX;

    const int threads = 256;
    const int blocks = 1216;
    mlp_mma_poly_kernel<<<blocks, threads>>>((const float2*)x, W_in, W_h, W_out,
                                             (float*)d_out, ntiles, pc);
}

// round 16
// speedup vs baseline: 1.1376x; 1.1376x over previous
#include <cuda_runtime.h>
#include <cuda_fp16.h>
#include <cmath>

// ---------------- half2 / MUFU helpers ----------------
__device__ __forceinline__ unsigned int h2u(__half2 h) {
    unsigned int u; memcpy(&u, &h, 4); return u;
}
__device__ __forceinline__ __half2 u2h(unsigned int u) {
    __half2 h; memcpy(&h, &u, 4); return h;
}
__device__ __forceinline__ unsigned int tanh_h2u(unsigned int x) {
    unsigned int r;
    asm("tanh.approx.f16x2 %0, %1;" : "=r"(r) : "r"(x));
    return r;
}
__device__ __forceinline__ float tanh_f32(float x) {
    float y;
    asm("tanh.approx.f32 %0, %1;" : "=f"(y) : "f"(x));
    return y;
}
// b_out is pre-scaled by 0.5, so sigmoid(2d) = 0.5 + 0.5*tanh(d): 2 instrs
__device__ __forceinline__ float sigmoid_prescaled(float half_x) {
    return fmaf(0.5f, tanh_f32(half_x), 0.5f);
}

// ---------------- mma: D[16,8] = A[16,8]*B[8,8] ----------------
__device__ __forceinline__ void mma8_f16(unsigned int& d0, unsigned int& d1,
                                         unsigned int a0, unsigned int a1,
                                         unsigned int b) {
    unsigned int r0, r1;
    asm("mma.sync.aligned.m16n8k8.row.col.f16.f16.f16.f16 "
        "{%0,%1}, {%2,%3}, {%4}, {%5,%6};"
        : "=r"(r0), "=r"(r1)
        : "r"(a0), "r"(a1), "r"(b), "r"(0u), "r"(0u));
    d0 = r0; d1 = r1;
}
__device__ __forceinline__ void mma8_f32(float& d0, float& d1, float& d2, float& d3,
                                         unsigned int a0, unsigned int a1,
                                         unsigned int b) {
    asm("mma.sync.aligned.m16n8k8.row.col.f32.f16.f16.f32 "
        "{%0,%1,%2,%3}, {%4,%5}, {%6}, {%7,%8,%9,%10};"
        : "=f"(d0), "=f"(d1), "=f"(d2), "=f"(d3)
        : "r"(a0), "r"(a1), "r"(b),
          "f"(0.0f), "f"(0.0f), "f"(0.0f), "f"(0.0f));
}

// tanh(x) ~= x * Q(t), t = (x/xmax)^2, Q = c0 + c1 t + ... + c5 t^5 (host-fitted,
// O(1) coefficients -> safe in f16). Input clamped to [-xmax, xmax].
struct PolyC { float c[6]; float xmax; };

#define TILP 4

__global__ void __launch_bounds__(256)
mlp_mma_poly_kernel(const float2* __restrict__ x2,
                    const float* __restrict__ W_in,
                    const float* __restrict__ W_h,
                    const float* __restrict__ W_out,
                    float* __restrict__ out,
                    int ntiles, PolyC pc)
{
    const int lane = threadIdx.x & 31;
    const int g = lane >> 2;   // 0..7
    const int c = lane & 3;    // 0..3
    const int warp = (blockIdx.x * blockDim.x + threadIdx.x) >> 5;
    const int nwarps = (gridDim.x * blockDim.x) >> 5;

    // B fragments: b = {W[g][2c], W[g][2c+1]}
    unsigned int b_in = (c == 0)
        ? h2u(__floats2half2_rn(__ldg(W_in + 2 * g), __ldg(W_in + 2 * g + 1)))
        : 0u;
    unsigned int b_h =
        h2u(__floats2half2_rn(__ldg(W_h + 8 * g + 2 * c), __ldg(W_h + 8 * g + 2 * c + 1)));
    // Output weights pre-scaled by 0.5 (folds the sigmoid's x/2)
    unsigned int b_out = (g < 3)
        ? h2u(__floats2half2_rn(0.5f * __ldg(W_out + 8 * g + 2 * c),
                                0.5f * __ldg(W_out + 8 * g + 2 * c + 1)))
        : 0u;

    // half2 poly constants (O(1) magnitudes, f16-safe)
    const __half2 C0 = __float2half2_rn(pc.c[0]);
    const __half2 C1 = __float2half2_rn(pc.c[1]);
    const __half2 C2 = __float2half2_rn(pc.c[2]);
    const __half2 C3 = __float2half2_rn(pc.c[3]);
    const __half2 C4 = __float2half2_rn(pc.c[4]);
    const __half2 C5 = __float2half2_rn(pc.c[5]);
    const __half2 PX = __float2half2_rn(pc.xmax);
    const __half2 NX = __float2half2_rn(-pc.xmax);
    const __half2 INV = __float2half2_rn(1.0f / pc.xmax);

    for (int t0 = warp * TILP; t0 < ntiles; t0 += nwarps * TILP) {
        unsigned int h0[TILP], h1[TILP];

        // ---- input layer: f16 mma + MUFU tanh ----
#pragma unroll
        for (int u = 0; u < TILP; u++) {
            int base = (t0 + u) * 16;
            float2 p0 = __ldg(x2 + base + g);
            float2 p1 = __ldg(x2 + base + 8 + g);
            unsigned int a0 = (c == 0) ? h2u(__floats2half2_rn(p0.x, p0.y)) : 0u;
            unsigned int a1 = (c == 0) ? h2u(__floats2half2_rn(p1.x, p1.y)) : 0u;
            unsigned int d0, d1;
            mma8_f16(d0, d1, a0, a1, b_in);
            h0[u] = tanh_h2u(d0);
            h1[u] = tanh_h2u(d1);
        }

        // ---- 4 hidden layers: alternate f16-Horner (fma pipe) / MUFU ----
#pragma unroll
        for (int l = 0; l < 4; l++) {
            if ((l & 1) == 0) {
                // POLY layer, fully in half2: clamp -> t=(x/xmax)^2 -> Horner -> x*Q
#pragma unroll
                for (int u = 0; u < TILP; u++) {
                    unsigned int d0, d1;
                    mma8_f16(d0, d1, h0[u], h1[u], b_h);
                    __half2 v0 = __hmin2(__hmax2(u2h(d0), NX), PX);
                    __half2 v1 = __hmin2(__hmax2(u2h(d1), NX), PX);
                    __half2 s0 = __hmul2(v0, INV);
                    __half2 s1 = __hmul2(v1, INV);
                    __half2 t0h = __hmul2(s0, s0);
                    __half2 t1h = __hmul2(s1, s1);
                    __half2 p0 = __hfma2(C5, t0h, C4);
                    __half2 p1 = __hfma2(C5, t1h, C4);
                    p0 = __hfma2(p0, t0h, C3);  p1 = __hfma2(p1, t1h, C3);
                    p0 = __hfma2(p0, t0h, C2);  p1 = __hfma2(p1, t1h, C2);
                    p0 = __hfma2(p0, t0h, C1);  p1 = __hfma2(p1, t1h, C1);
                    p0 = __hfma2(p0, t0h, C0);  p1 = __hfma2(p1, t1h, C0);
                    h0[u] = h2u(__hmul2(p0, v0));
                    h1[u] = h2u(__hmul2(p1, v1));
                }
            } else {
                // MUFU layer
#pragma unroll
                for (int u = 0; u < TILP; u++) {
                    unsigned int d0, d1;
                    mma8_f16(d0, d1, h0[u], h1[u], b_h);
                    h0[u] = tanh_h2u(d0);
                    h1[u] = tanh_h2u(d1);
                }
            }
        }

        // ---- output layer (weights pre-halved) + sigmoid + scalar stores ----
#pragma unroll
        for (int u = 0; u < TILP; u++) {
            float d0, d1, d2, d3;
            mma8_f32(d0, d1, d2, d3, h0[u], h1[u], b_out);
            int base = (t0 + u) * 16;
            if (c < 2) {
                float s0 = sigmoid_prescaled(d0);
                float s1 = sigmoid_prescaled(d1);
                float s2 = sigmoid_prescaled(d2);
                float s3 = sigmoid_prescaled(d3);
                long long r0 = base + g;
                long long r1 = base + 8 + g;
                if (c == 0) {
                    out[r0 * 3 + 0] = s0;
                    out[r0 * 3 + 1] = s1;
                    out[r1 * 3 + 0] = s2;
                    out[r1 * 3 + 1] = s3;
                } else {
                    out[r0 * 3 + 2] = s0;
                    out[r1 * 3 + 2] = s2;
                }
            }
        }
    }
}

// ---------------- host: weighted LS fit of tanh(x)/x as Q(t), t=(x/xmax)^2 ----
static void fit_tanh_poly_t(double xmax, float* cf, int NCc) {
    const int NS = 6000;
    double ATA[8][8] = {{0}}, ATy[8] = {0};
    for (int j = 1; j <= NS; j++) {
        double x = xmax * j / NS;
        double t = (x / xmax) * (x / xmax);
        double y = tanh(x) / x;
        double w2 = x * x;  // minimize absolute tanh error in L2
        double pt[8];
        pt[0] = 1.0;
        for (int i = 1; i < NCc; i++) pt[i] = pt[i - 1] * t;
        for (int a = 0; a < NCc; a++) {
            for (int b = 0; b < NCc; b++) ATA[a][b] += w2 * pt[a] * pt[b];
            ATy[a] += w2 * pt[a] * y;
        }
    }
    for (int k = 0; k < NCc; k++) {
        int piv = k;
        for (int r = k + 1; r < NCc; r++)
            if (fabs(ATA[r][k]) > fabs(ATA[piv][k])) piv = r;
        if (piv != k) {
            for (int cc = 0; cc < NCc; cc++) {
                double tt = ATA[k][cc]; ATA[k][cc] = ATA[piv][cc]; ATA[piv][cc] = tt;
            }
            double tt = ATy[k]; ATy[k] = ATy[piv]; ATy[piv] = tt;
        }
        for (int r = k + 1; r < NCc; r++) {
            double f = ATA[r][k] / ATA[k][k];
            for (int cc = k; cc < NCc; cc++) ATA[r][cc] -= f * ATA[k][cc];
            ATy[r] -= f * ATy[k];
        }
    }
    double sol[8];
    for (int k = NCc - 1; k >= 0; k--) {
        double s = ATy[k];
        for (int cc = k + 1; cc < NCc; cc++) s -= ATA[k][cc] * sol[cc];
        sol[k] = s / ATA[k][k];
    }
    for (int i = 0; i < NCc; i++) cf[i] = (float)sol[i];
}

extern "C" void kernel_launch(void* const* d_in, const int* in_sizes, int n_in,
                              void* d_out, int out_size)
{
    const float* x     = (const float*)d_in[0];  // [N, 2]
    const float* W_in  = (const float*)d_in[1];  // [8, 2]
    const float* W_h   = (const float*)d_in[2];  // [8, 8]
    const float* W_out = (const float*)d_in[3];  // [3, 8]

    int n_pixels = in_sizes[0] / 2;      // 16777216
    int ntiles = n_pixels / 16;          // 1048576, divisible by TILP=4

    const double XMAX = 3.35;
    PolyC pc;
    fit_tanh_poly_t(XMAX, pc.c, 6);
    pc.xmax = (float)XMAX;

    const int threads = 256;
    const int blocks = 1216;
    mlp_mma_poly_kernel<<<blocks, threads>>>((const float2*)x, W_in, W_h, W_out,
                                             (float*)d_out, ntiles, pc);
}